// round 4
// baseline (speedup 1.0000x reference)
#include <cuda_runtime.h>
#include <math.h>

#define NN 65536
#define NT 131072
#define MD 256
#define TC 1024
#define MAXLVL 1024
#define NBLK 128
// dynamic smem: ws 256*64 floats + Hs 128*257 floats
#define SMEM_MAIN ((256*64 + 128*257) * 4)

// ---------------- device scratch (static; allowed) ----------------
__device__ float g_ttab[1000 * TC];
__device__ float g_Y[134217728];        // [NT][1024] per-node projection y = h @ [Wiouh|Wfh]
__device__ float g_H[NT * MD];
__device__ float g_C[NT * MD];
__device__ int   g_depth[NT];
__device__ int   g_tok[NT];
__device__ int   g_pc[NT];
__device__ int   g_lvlcnt[MAXLVL];
__device__ int   g_lvloff[MAXLVL + 1];
__device__ int   g_lvlcur[MAXLVL];
__device__ int   g_ccnt[NT];
__device__ int   g_csroff[NT + 1];
__device__ int   g_csrcur[NT];
__device__ int   g_order[NT];
__device__ int   g_child[NT];
__device__ int   g_maxd;
__device__ unsigned g_cnt = 0;
__device__ unsigned g_gen = 0;

__device__ __forceinline__ float sigm(float x) { return 1.f / (1.f + __expf(-x)); }

__device__ __forceinline__ void gsync() {
    __syncthreads();
    if (threadIdx.x == 0) {
        __threadfence();
        unsigned gen = *(volatile unsigned*)&g_gen;
        if (atomicAdd(&g_cnt, 1u) == gridDim.x - 1u) {
            g_cnt = 0;
            __threadfence();
            atomicExch(&g_gen, gen + 1u);
        } else {
            while (*(volatile unsigned*)&g_gen == gen) { __nanosleep(64); }
        }
        __threadfence();
    }
    __syncthreads();
}

// ---------------- setup kernels ----------------
__global__ void k_zero() {
    int i = blockIdx.x * 256 + threadIdx.x;
    if (i < NT) g_ccnt[i] = 0;
    if (i < MAXLVL) g_lvlcnt[i] = 0;
    if (i == 0) g_maxd = 0;
}

// ttab[t][c] = emb[t] @ [Wioux | Wfx] + (bioux+biouh | bfx+bfh)
__global__ void k_tables(const float* __restrict__ emb, const float* __restrict__ Wioux,
                         const float* __restrict__ bioux, const float* __restrict__ biouh,
                         const float* __restrict__ Wfx, const float* __restrict__ bfx,
                         const float* __restrict__ bfh) {
    __shared__ float wsx[256 * 32];
    __shared__ float es[8 * 256];
    int cgb = blockIdx.x & 31;   // 32 col groups of 32
    int tg  = blockIdx.x >> 5;   // 4 token groups of 250
    int tid = threadIdx.x;
    int C0 = cgb * 32;
    for (int idx = tid; idx < 256 * 32; idx += 256) {
        int k = idx >> 5, c = idx & 31;
        int C = C0 + c;
        wsx[idx] = (C < 768) ? Wioux[k * 768 + C] : Wfx[k * 256 + (C - 768)];
    }
    int c = tid & 31, s = tid >> 5;
    int C = C0 + c;
    float bias = (C < 768) ? (bioux[C] + biouh[C]) : (bfx[C - 768] + bfh[C - 768]);
    int t0 = tg * 250;
    for (int tt = 0; tt < 250; tt += 8) {
        __syncthreads();
        for (int idx = tid; idx < 8 * 256; idx += 256) {
            int r = idx >> 8, k = idx & 255;
            int tok = t0 + tt + r;
            es[idx] = (tt + r < 250) ? emb[tok * 256 + k] : 0.f;
        }
        __syncthreads();
        if (tt + s < 250) {
            int tok = t0 + tt + s;
            float acc = bias;
            const float* ep = es + s * 256;
#pragma unroll 8
            for (int k = 0; k < 256; ++k) acc = fmaf(ep[k], wsx[k * 32 + c], acc);
            g_ttab[tok * TC + C] = acc;
        }
    }
}

__global__ void k_depth(const int* __restrict__ lt, const int* __restrict__ lp,
                        const int* __restrict__ rt, const int* __restrict__ rp) {
    int i = blockIdx.x * 256 + threadIdx.x;
    if (i >= NT) return;
    int tree = i >> 16, loc = i & 65535;
    const int* par = tree ? rp : lp;
    const int* tok = tree ? rt : lt;
    g_tok[i] = tok[loc];
    int d = 0, j = loc;
    while (j != 0) { j = par[j]; d++; }
    g_depth[i] = d;
    atomicMax(&g_maxd, d);
    atomicAdd(&g_lvlcnt[d], 1);
    if (loc != 0) {
        int p = (tree << 16) + par[loc];
        g_pc[i] = p;
        atomicAdd(&g_ccnt[p], 1);
    } else {
        g_pc[i] = -1;
    }
}

__global__ void k_scan() {
    __shared__ int ps[1024];
    int t = threadIdx.x;
    // CSR offsets: scan of child counts
    int base = t * (NT / 1024);
    int s = 0;
    for (int x = 0; x < NT / 1024; x++) s += g_ccnt[base + x];
    ps[t] = s; __syncthreads();
    for (int off = 1; off < 1024; off <<= 1) {
        int v = (t >= off) ? ps[t - off] : 0;
        __syncthreads();
        ps[t] += v;
        __syncthreads();
    }
    int run = ps[t] - s;
    for (int x = 0; x < NT / 1024; x++) {
        g_csroff[base + x] = run;
        g_csrcur[base + x] = run;
        run += g_ccnt[base + x];
    }
    if (t == 1023) g_csroff[NT] = run;
    __syncthreads();
    // level offsets: scan of depth histogram
    int lv = g_lvlcnt[t];
    ps[t] = lv; __syncthreads();
    for (int off = 1; off < 1024; off <<= 1) {
        int v = (t >= off) ? ps[t - off] : 0;
        __syncthreads();
        ps[t] += v;
        __syncthreads();
    }
    g_lvloff[t] = ps[t] - lv;
    g_lvlcur[t] = ps[t] - lv;
    if (t == 1023) g_lvloff[MAXLVL] = ps[1023];
}

__global__ void k_scatter() {
    int i = blockIdx.x * 256 + threadIdx.x;
    if (i >= NT) return;
    int q = atomicAdd(&g_lvlcur[g_depth[i]], 1);
    g_order[q] = i;
    int p = g_pc[i];
    if (p >= 0) g_child[atomicAdd(&g_csrcur[p], 1)] = i;
}

// sort each node's child list ascending -> deterministic gather order
__global__ void k_sortchild() {
    int i = blockIdx.x * 256 + threadIdx.x;
    if (i >= NT) return;
    int b = g_csroff[i], e = g_csroff[i + 1];
    for (int x = b + 1; x < e; x++) {
        int v = g_child[x];
        int y = x - 1;
        while (y >= b && g_child[y] > v) { g_child[y + 1] = g_child[y]; y--; }
        g_child[y + 1] = v;
    }
}

// ---------------- persistent main kernel ----------------
__global__ void __launch_bounds__(256, 1)
k_main(const float* __restrict__ Wiouh, const float* __restrict__ Wfh,
       const float* __restrict__ Wh, const float* __restrict__ bh,
       const float* __restrict__ Wp, const float* __restrict__ bp,
       float* __restrict__ out) {
    extern __shared__ float sm[];
    float* ws = sm;                 // [256][64]  this block's columns of [Wiouh|Wfh]
    float* Hs = sm + 256 * 64;      // [128][257] staged H tile (row stride 257)
    __shared__ int sOrd[128];
    int tid = threadIdx.x;
    int b = blockIdx.x;
    int cg = b & 15, rg = b >> 4;   // 16 col groups x 8 row groups
    int colbase = cg * 64;

    for (int idx = tid; idx < 256 * 64; idx += 256) {
        int k = idx >> 6, c = idx & 63;
        int C = colbase + c;
        ws[idx] = (C < 768) ? Wiouh[k * 768 + C] : Wfh[k * 256 + (C - 768)];
    }
    __syncthreads();

    int Dmax = g_maxd;
    for (int d = Dmax; d >= 0; --d) {
        int s = g_lvloff[d], e = g_lvloff[d + 1];
        // ---- gate phase: one block per node ----
        for (int q = s + b; q < e; q += (int)gridDim.x) {
            int node = g_order[q];
            const float* tr = g_ttab + (size_t)g_tok[node] * TC;
            float i0 = tr[tid], i1 = tr[256 + tid], i2 = tr[512 + tid];
            float fxp = tr[768 + tid];
            float fc = 0.f;
            int cb = g_csroff[node], ce = g_csroff[node + 1];
            for (int x = cb; x < ce; ++x) {
                int ch = g_child[x];
                const float* yr = g_Y + (size_t)ch * TC;
                i0 += yr[tid]; i1 += yr[256 + tid]; i2 += yr[512 + tid];
                float f = sigm(yr[768 + tid] + fxp);
                fc = fmaf(f, g_C[(size_t)ch * MD + tid], fc);
            }
            float cc = sigm(i0) * tanhf(i2) + fc;
            float hh = sigm(i1) * tanhf(cc);
            g_C[(size_t)node * MD + tid] = cc;
            g_H[(size_t)node * MD + tid] = hh;
        }
        gsync();
        // ---- matvec phase: Y_level = H_level @ [Wiouh|Wfh] ----
        if (d > 0) {
            int nLev = e - s;
            int ntiles = (nLev + 127) >> 7;
            for (int t = rg; t < ntiles; t += 8) {
                int tbase = s + (t << 7);
                int cnt = min(128, e - tbase);
                if (tid < 128) sOrd[tid] = (tid < cnt) ? g_order[tbase + tid] : 0;
                __syncthreads();
                for (int idx = tid; idx < 128 * 256; idx += 256) {
                    int n = idx >> 8, k = idx & 255;
                    Hs[n * 257 + k] = (n < cnt) ? g_H[(size_t)sOrd[n] * MD + k] : 0.f;
                }
                __syncthreads();
                int cq = tid & 15, nq = tid >> 4;   // warp: 2 nq values, 16 cq
                float4 a[8];
#pragma unroll
                for (int r = 0; r < 8; r++) a[r] = make_float4(0.f, 0.f, 0.f, 0.f);
                const float4* wsv = (const float4*)ws;
                const float* h0 = Hs + (nq * 8) * 257;
#pragma unroll 4
                for (int k = 0; k < 256; ++k) {
                    float4 w = wsv[k * 16 + cq];
                    float hv[8];
#pragma unroll
                    for (int r = 0; r < 8; r++) hv[r] = h0[r * 257 + k];
#pragma unroll
                    for (int r = 0; r < 8; r++) {
                        a[r].x = fmaf(hv[r], w.x, a[r].x);
                        a[r].y = fmaf(hv[r], w.y, a[r].y);
                        a[r].z = fmaf(hv[r], w.z, a[r].z);
                        a[r].w = fmaf(hv[r], w.w, a[r].w);
                    }
                }
#pragma unroll
                for (int r = 0; r < 8; r++) {
                    int n = nq * 8 + r;
                    if (n < cnt) {
                        float4* dst = (float4*)(g_Y + (size_t)sOrd[n] * TC + colbase + cq * 4);
                        *dst = a[r];
                    }
                }
                __syncthreads();
            }
        }
        gsync();
    }

    // ---- similarity head (block 0) ----
    if (b == 0) {
        float* vec = sm;            // [512]
        float* hid = sm + 512;      // [256]
        float* red = sm + 768;      // [512]
        float cl = g_C[tid];
        float cr = g_C[(size_t)65536 * MD + tid];
        vec[tid] = cl * cr;
        vec[256 + tid] = fabsf(cl - cr);
        __syncthreads();
        float acc = bh[tid];
        for (int k = 0; k < 512; ++k) acc = fmaf(vec[k], Wh[k * 256 + tid], acc);
        hid[tid] = sigm(acc);
        __syncthreads();
        red[tid] = hid[tid] * Wp[tid * 2 + 0];
        red[256 + tid] = hid[tid] * Wp[tid * 2 + 1];
        __syncthreads();
        for (int off = 128; off > 0; off >>= 1) {
            if (tid < off) {
                red[tid] += red[tid + off];
                red[256 + tid] += red[256 + tid + off];
            }
            __syncthreads();
        }
        if (tid == 0) {
            float l0 = red[0] + bp[0];
            float l1 = red[256] + bp[1];
            float m = fmaxf(l0, l1);
            float e0 = expf(l0 - m), e1 = expf(l1 - m);
            float inv = 1.f / (e0 + e1);
            out[0] = e0 * inv;
            out[1] = e1 * inv;
        }
    }
}

extern "C" void kernel_launch(void* const* d_in, const int* in_sizes, int n_in,
                              void* d_out, int out_size) {
    const int*   lt    = (const int*)d_in[0];
    const int*   lp    = (const int*)d_in[1];
    const int*   rt    = (const int*)d_in[2];
    const int*   rp    = (const int*)d_in[3];
    const float* emb   = (const float*)d_in[4];
    const float* Wioux = (const float*)d_in[5];
    const float* bioux = (const float*)d_in[6];
    const float* Wiouh = (const float*)d_in[7];
    const float* biouh = (const float*)d_in[8];
    const float* Wfx   = (const float*)d_in[9];
    const float* bfx   = (const float*)d_in[10];
    const float* Wfh   = (const float*)d_in[11];
    const float* bfh   = (const float*)d_in[12];
    const float* Wh    = (const float*)d_in[13];
    const float* bh    = (const float*)d_in[14];
    const float* Wp    = (const float*)d_in[15];
    const float* bp    = (const float*)d_in[16];
    float* out = (float*)d_out;

    cudaFuncSetAttribute(k_main, cudaFuncAttributeMaxDynamicSharedMemorySize, SMEM_MAIN);

    k_zero<<<NT / 256, 256>>>();
    k_tables<<<128, 256>>>(emb, Wioux, bioux, biouh, Wfx, bfx, bfh);
    k_depth<<<NT / 256, 256>>>(lt, lp, rt, rp);
    k_scan<<<1, 1024>>>();
    k_scatter<<<NT / 256, 256>>>();
    k_sortchild<<<NT / 256, 256>>>();
    k_main<<<NBLK, 256, SMEM_MAIN>>>(Wiouh, Wfh, Wh, bh, Wp, bp, out);
}